// round 1
// baseline (speedup 1.0000x reference)
#include <cuda_runtime.h>
#include <cuda_bf16.h>
#include <stdint.h>

// Problem constants
#define E_TOTAL   1600000
#define N_NODES   100000
#define NODE_DIM  64
#define EDGE_DIM  32
#define IN_DIM    160     // 2*64+32
#define HID       128
#define OUT_DIM   64
#define TILE_E    64      // edges per block-tile (8 warps * 8 edges)
#define NTILES    (E_TOTAL / TILE_E)  // 25000
#define EPW       8       // edges per warp

// smem layout (floats)
#define W1T_STRIDE 162    // even (8B-aligned u64 loads) and 162%32==2 -> conflict-free lane-strided LDS.64
#define W2T_STRIDE 130
#define W1T_FLOATS (HID * W1T_STRIDE)        // 20736
#define W2T_FLOATS (OUT_DIM * W2T_STRIDE)    // 8320
#define MRG_FLOATS (8 * EPW * IN_DIM)        // 10240
#define H_FLOATS   (8 * EPW * HID)           // 8192
#define SMEM_FLOATS (W1T_FLOATS + W2T_FLOATS + MRG_FLOATS + H_FLOATS)  // 47488
#define SMEM_BYTES  (SMEM_FLOATS * 4)        // 189952

typedef unsigned long long u64;

__device__ __forceinline__ u64 fma2(u64 a, u64 b, u64 c) {
    u64 d;
    asm("fma.rn.f32x2 %0, %1, %2, %3;" : "=l"(d) : "l"(a), "l"(b), "l"(c));
    return d;
}
__device__ __forceinline__ u64 pack2(float lo, float hi) {
    u64 d;
    asm("mov.b64 %0, {%1, %2};" : "=l"(d) : "f"(lo), "f"(hi));
    return d;
}
__device__ __forceinline__ float2 unpack2(u64 v) {
    float2 r;
    asm("mov.b64 {%0, %1}, %2;" : "=f"(r.x), "=f"(r.y) : "l"(v));
    return r;
}

// edge_index dtype probe: reference declares int64, but JAX without x64 gives int32.
// If int64: values < 1e5 so every high 32-bit word is 0. If int32: the "odd" 32-bit
// words are themselves random indices in [0,1e5) -> OR over 2048 of them is nonzero
// with probability 1 - 1e-5^2048 (i.e. always, deterministically for a fixed input).
__device__ int g_idx_is32;

__global__ void detect_idx_dtype_kernel(const unsigned int* __restrict__ a) {
    unsigned v = 0;
    for (int i = threadIdx.x; i < 2048; i += blockDim.x)
        v |= a[2 * i + 1];
    int any = __syncthreads_or(v != 0);
    if (threadIdx.x == 0) g_idx_is32 = any ? 1 : 0;
}

__global__ void __launch_bounds__(256, 1)
edge_mlp_kernel(const float* __restrict__ x,
                const float* __restrict__ ea,
                const float* __restrict__ W1,
                const float* __restrict__ b1,
                const float* __restrict__ W2,
                const float* __restrict__ b2,
                const void*  __restrict__ eidx,
                float* __restrict__ out)
{
    extern __shared__ float sm[];
    float* W1T = sm;                               // [HID][W1T_STRIDE], W1T[j][k]
    float* W2T = W1T + W1T_FLOATS;                 // [OUT][W2T_STRIDE], W2T[o][k]
    float* mergedAll = W2T + W2T_FLOATS;           // 8 warps x [8][160]
    float* hAll = mergedAll + MRG_FLOATS;          // 8 warps x [8][128]

    const int tid  = threadIdx.x;
    const int warp = tid >> 5;
    const int lane = tid & 31;

    // Stage transposed weights (k contiguous -> natural u64 k-pair loads)
    for (int i = tid; i < IN_DIM * HID; i += 256) {
        int k = i >> 7, j = i & 127;               // W1 is [160][128]
        W1T[j * W1T_STRIDE + k] = W1[i];
    }
    for (int i = tid; i < HID * OUT_DIM; i += 256) {
        int k = i >> 6, o = i & 63;                // W2 is [128][64]
        W2T[o * W2T_STRIDE + k] = W2[i];
    }
    __syncthreads();

    const int is32 = g_idx_is32;
    const int* e32 = (const int*)eidx;
    const long long* e64 = (const long long*)eidx;

    float* mw = mergedAll + warp * (EPW * IN_DIM);
    float* hw = hAll + warp * (EPW * HID);

    float b1v[4], b2v[2];
#pragma unroll
    for (int ji = 0; ji < 4; ji++) b1v[ji] = b1[lane + 32 * ji];
    b2v[0] = b2[lane];
    b2v[1] = b2[lane + 32];

    for (int t = blockIdx.x; t < NTILES; t += gridDim.x) {
        const int ebase = t * TILE_E + warp * EPW;

        // ---- gather src/tgt indices (lanes 0..7 hold them, shfl to distribute) ----
        long long s8 = 0, t8 = 0;
        if (lane < EPW) {
            int e = ebase + lane;
            if (is32) { s8 = e32[e]; t8 = e32[E_TOTAL + e]; }
            else      { s8 = e64[e]; t8 = e64[E_TOTAL + e]; }
        }

        // ---- gather merged = [x[src] | x[tgt] | edge_attr] : 8 edges x 40 float4 ----
#pragma unroll
        for (int i = 0; i < 10; i++) {
            int idx = lane + 32 * i;               // 0..319
            int e = idx / 40;
            int q = idx - e * 40;
            long long se = __shfl_sync(0xffffffffu, s8, e);
            long long te = __shfl_sync(0xffffffffu, t8, e);
            float4 v;
            if (q < 16)      v = ((const float4*)(x + se * NODE_DIM))[q];
            else if (q < 32) v = ((const float4*)(x + te * NODE_DIM))[q - 16];
            else             v = ((const float4*)(ea + (long long)(ebase + e) * EDGE_DIM))[q - 32];
            *(float4*)(mw + e * IN_DIM + q * 4) = v;
        }
        __syncwarp();

        // ---- layer 1: h[e][j] = relu(b1[j] + sum_k merged[e][k]*W1[k][j]) ----
        // f32x2 pairs over K: acc halves hold even-k / odd-k partial sums.
        // lane covers j in {lane, lane+32, lane+64, lane+96}.
        u64 acc[EPW][4];
#pragma unroll
        for (int e = 0; e < EPW; e++)
#pragma unroll
            for (int ji = 0; ji < 4; ji++)
                acc[e][ji] = pack2(b1v[ji], 0.0f);

#pragma unroll 2
        for (int kk2 = 0; kk2 < IN_DIM / 4; kk2++) {   // 40 iters, 4 k's each
            u64 wa[4], wb[4];
#pragma unroll
            for (int ji = 0; ji < 4; ji++) {
                const float* wp = W1T + (lane + 32 * ji) * W1T_STRIDE + 4 * kk2;
                wa[ji] = *(const u64*)(wp);
                wb[ji] = *(const u64*)(wp + 2);
            }
#pragma unroll
            for (int e = 0; e < EPW; e++) {
                ulonglong2 m2 = *(const ulonglong2*)(mw + e * IN_DIM + 4 * kk2);  // LDS.128 broadcast
#pragma unroll
                for (int ji = 0; ji < 4; ji++) {
                    acc[e][ji] = fma2(m2.x, wa[ji], acc[e][ji]);
                    acc[e][ji] = fma2(m2.y, wb[ji], acc[e][ji]);
                }
            }
        }

        // relu, fold pair halves, store h
#pragma unroll
        for (int e = 0; e < EPW; e++)
#pragma unroll
            for (int ji = 0; ji < 4; ji++) {
                float2 p = unpack2(acc[e][ji]);
                hw[e * HID + lane + 32 * ji] = fmaxf(p.x + p.y, 0.0f);
            }
        __syncwarp();

        // ---- layer 2: out[e][o] = b2[o] + sum_k h[e][k]*W2[k][o] ----
        // lane covers o in {lane, lane+32}
        u64 a2[EPW][2];
#pragma unroll
        for (int e = 0; e < EPW; e++) { a2[e][0] = 0ull; a2[e][1] = 0ull; }

#pragma unroll 2
        for (int kk2 = 0; kk2 < HID / 4; kk2++) {      // 32 iters
            const float* wp0 = W2T + lane * W2T_STRIDE + 4 * kk2;
            const float* wp1 = W2T + (lane + 32) * W2T_STRIDE + 4 * kk2;
            u64 w0a = *(const u64*)(wp0);
            u64 w0b = *(const u64*)(wp0 + 2);
            u64 w1a = *(const u64*)(wp1);
            u64 w1b = *(const u64*)(wp1 + 2);
#pragma unroll
            for (int e = 0; e < EPW; e++) {
                ulonglong2 h2 = *(const ulonglong2*)(hw + e * HID + 4 * kk2);  // LDS.128 broadcast
                a2[e][0] = fma2(h2.x, w0a, a2[e][0]);
                a2[e][0] = fma2(h2.y, w0b, a2[e][0]);
                a2[e][1] = fma2(h2.x, w1a, a2[e][1]);
                a2[e][1] = fma2(h2.y, w1b, a2[e][1]);
            }
        }

        // ---- epilogue: fold halves, add bias, coalesced store ----
#pragma unroll
        for (int e = 0; e < EPW; e++) {
            float2 p0 = unpack2(a2[e][0]);
            float2 p1 = unpack2(a2[e][1]);
            size_t ob = (size_t)(ebase + e) * OUT_DIM;
            out[ob + lane]      = p0.x + p0.y + b2v[0];
            out[ob + lane + 32] = p1.x + p1.y + b2v[1];
        }
        __syncwarp();   // before next tile overwrites mw/hw
    }
}

extern "C" void kernel_launch(void* const* d_in, const int* in_sizes, int n_in,
                              void* d_out, int out_size)
{
    const float* x  = (const float*)d_in[0];
    const float* ea = (const float*)d_in[1];
    const float* W1 = (const float*)d_in[2];
    const float* b1 = (const float*)d_in[3];
    const float* W2 = (const float*)d_in[4];
    const float* b2 = (const float*)d_in[5];
    const void*  ei = d_in[6];
    float* out = (float*)d_out;

    cudaFuncSetAttribute(edge_mlp_kernel,
                         cudaFuncAttributeMaxDynamicSharedMemorySize, SMEM_BYTES);

    detect_idx_dtype_kernel<<<1, 256>>>((const unsigned int*)ei);
    edge_mlp_kernel<<<1520, 256, SMEM_BYTES>>>(x, ea, W1, b1, W2, b2, ei, out);
}

// round 4
// speedup vs baseline: 1.0577x; 1.0577x over previous
#include <cuda_runtime.h>
#include <cuda_bf16.h>
#include <stdint.h>

// Problem constants
#define E_TOTAL   1600000
#define N_NODES   100000
#define NODE_DIM  64
#define EDGE_DIM  32
#define IN_DIM    160     // 2*64+32
#define HID       128
#define OUT_DIM   64
#define NWARPS    16
#define NTHREADS  512
#define EPW       4       // edges per warp
#define TILE_E    (NWARPS * EPW)        // 64
#define NTILES    (E_TOTAL / TILE_E)    // 25000

// smem layout (floats)
// strides ≡ 4 (mod 32) -> conflict-free lane-strided LDS.128 (lane L covers banks 4L..4L+3)
#define W1T_STRIDE 164
#define W2T_STRIDE 132
#define W1T_FLOATS (HID * W1T_STRIDE)          // 20992
#define W2T_FLOATS (OUT_DIM * W2T_STRIDE)      // 8448
#define MRG_FLOATS (NWARPS * EPW * IN_DIM)     // 10240
#define H_FLOATS   (NWARPS * EPW * HID)        // 8192
#define SMEM_FLOATS (W1T_FLOATS + W2T_FLOATS + MRG_FLOATS + H_FLOATS)  // 47872
#define SMEM_BYTES  (SMEM_FLOATS * 4)          // 191488

typedef unsigned long long u64;

__device__ __forceinline__ u64 fma2(u64 a, u64 b, u64 c) {
    u64 d;
    asm("fma.rn.f32x2 %0, %1, %2, %3;" : "=l"(d) : "l"(a), "l"(b), "l"(c));
    return d;
}
__device__ __forceinline__ u64 pack2(float lo, float hi) {
    u64 d;
    asm("mov.b64 %0, {%1, %2};" : "=l"(d) : "f"(lo), "f"(hi));
    return d;
}
__device__ __forceinline__ float2 unpack2(u64 v) {
    float2 r;
    asm("mov.b64 {%0, %1}, %2;" : "=f"(r.x), "=f"(r.y) : "l"(v));
    return r;
}

// edge_index dtype probe: reference declares int64, but if the pipeline delivers
// int32 the "high words" are themselves random indices -> OR over 2048 of them is
// nonzero (deterministic for a fixed input; indices < 1e5 so true int64 high words
// are all zero).
__device__ int g_idx_is32;

__global__ void detect_idx_dtype_kernel(const unsigned int* __restrict__ a) {
    unsigned v = 0;
    for (int i = threadIdx.x; i < 2048; i += blockDim.x)
        v |= a[2 * i + 1];
    int any = __syncthreads_or(v != 0);
    if (threadIdx.x == 0) g_idx_is32 = any ? 1 : 0;
}

__global__ void __launch_bounds__(NTHREADS, 1)
edge_mlp_kernel(const float* __restrict__ x,
                const float* __restrict__ ea,
                const float* __restrict__ W1,
                const float* __restrict__ b1,
                const float* __restrict__ W2,
                const float* __restrict__ b2,
                const void*  __restrict__ eidx,
                float* __restrict__ out)
{
    extern __shared__ float sm[];
    float* W1T = sm;                               // [HID][W1T_STRIDE], W1T[j][k]
    float* W2T = W1T + W1T_FLOATS;                 // [OUT][W2T_STRIDE], W2T[o][k]
    float* mergedAll = W2T + W2T_FLOATS;           // NWARPS x [EPW][160]
    float* hAll = mergedAll + MRG_FLOATS;          // NWARPS x [EPW][128]

    const int tid  = threadIdx.x;
    const int warp = tid >> 5;
    const int lane = tid & 31;

    // Stage transposed weights via float4 global loads (k contiguous in smem)
    // W1 is [160][128]: each float4 covers j..j+3 of one k row.
    for (int i = tid; i < (IN_DIM * HID) / 4; i += NTHREADS) {
        int k = i >> 5;                 // 128/4 = 32 quads per row
        int j4 = (i & 31) * 4;
        float4 v = ((const float4*)W1)[i];
        W1T[(j4 + 0) * W1T_STRIDE + k] = v.x;
        W1T[(j4 + 1) * W1T_STRIDE + k] = v.y;
        W1T[(j4 + 2) * W1T_STRIDE + k] = v.z;
        W1T[(j4 + 3) * W1T_STRIDE + k] = v.w;
    }
    // W2 is [128][64]
    for (int i = tid; i < (HID * OUT_DIM) / 4; i += NTHREADS) {
        int k = i >> 4;                 // 64/4 = 16 quads per row
        int o4 = (i & 15) * 4;
        float4 v = ((const float4*)W2)[i];
        W2T[(o4 + 0) * W2T_STRIDE + k] = v.x;
        W2T[(o4 + 1) * W2T_STRIDE + k] = v.y;
        W2T[(o4 + 2) * W2T_STRIDE + k] = v.z;
        W2T[(o4 + 3) * W2T_STRIDE + k] = v.w;
    }
    __syncthreads();

    const int is32 = g_idx_is32;
    const int* e32 = (const int*)eidx;
    const long long* e64 = (const long long*)eidx;

    float* mw = mergedAll + warp * (EPW * IN_DIM);
    float* hw = hAll + warp * (EPW * HID);

    float b1v[4], b2v[2];
#pragma unroll
    for (int ji = 0; ji < 4; ji++) b1v[ji] = b1[lane + 32 * ji];
    b2v[0] = b2[lane];
    b2v[1] = b2[lane + 32];

    for (int t = blockIdx.x; t < NTILES; t += gridDim.x) {
        const int ebase = t * TILE_E + warp * EPW;

        // ---- gather src/tgt indices (lanes 0..3 hold them, shfl to distribute) ----
        long long s8 = 0, t8 = 0;
        if (lane < EPW) {
            int e = ebase + lane;
            if (is32) { s8 = e32[e]; t8 = e32[E_TOTAL + e]; }
            else      { s8 = e64[e]; t8 = e64[E_TOTAL + e]; }
        }

        // ---- gather merged = [x[src] | x[tgt] | edge_attr] : 4 edges x 40 float4 ----
#pragma unroll
        for (int i = 0; i < 5; i++) {
            int idx = lane + 32 * i;               // 0..159
            int e = idx / 40;
            int q = idx - e * 40;
            long long se = __shfl_sync(0xffffffffu, s8, e);
            long long te = __shfl_sync(0xffffffffu, t8, e);
            float4 v;
            if (q < 16)      v = ((const float4*)(x + se * NODE_DIM))[q];
            else if (q < 32) v = ((const float4*)(x + te * NODE_DIM))[q - 16];
            else             v = ((const float4*)(ea + (long long)(ebase + e) * EDGE_DIM))[q - 32];
            *(float4*)(mw + e * IN_DIM + q * 4) = v;
        }
        __syncwarp();

        // ---- layer 1: h[e][j] = relu(b1[j] + sum_k merged[e][k]*W1[k][j]) ----
        // f32x2 pairs over K: acc halves hold even-k / odd-k partial sums.
        // lane covers j in {lane, lane+32, lane+64, lane+96}.
        u64 acc[EPW][4];
#pragma unroll
        for (int e = 0; e < EPW; e++)
#pragma unroll
            for (int ji = 0; ji < 4; ji++)
                acc[e][ji] = pack2(b1v[ji], 0.0f);

#pragma unroll 2
        for (int kk2 = 0; kk2 < IN_DIM / 4; kk2++) {   // 40 iters, 4 k's each
            u64 wa[4], wb[4];
#pragma unroll
            for (int ji = 0; ji < 4; ji++) {
                // LDS.128: k-quad of W1T row (16B aligned, conflict-free stride)
                ulonglong2 w2q = *(const ulonglong2*)(W1T + (lane + 32 * ji) * W1T_STRIDE + 4 * kk2);
                wa[ji] = w2q.x;
                wb[ji] = w2q.y;
            }
#pragma unroll
            for (int e = 0; e < EPW; e++) {
                ulonglong2 m2 = *(const ulonglong2*)(mw + e * IN_DIM + 4 * kk2);  // LDS.128 broadcast
#pragma unroll
                for (int ji = 0; ji < 4; ji++) {
                    acc[e][ji] = fma2(m2.x, wa[ji], acc[e][ji]);
                    acc[e][ji] = fma2(m2.y, wb[ji], acc[e][ji]);
                }
            }
        }

        // relu, fold pair halves, store h
#pragma unroll
        for (int e = 0; e < EPW; e++)
#pragma unroll
            for (int ji = 0; ji < 4; ji++) {
                float2 p = unpack2(acc[e][ji]);
                hw[e * HID + lane + 32 * ji] = fmaxf(p.x + p.y, 0.0f);
            }
        __syncwarp();

        // ---- layer 2: out[e][o] = b2[o] + sum_k h[e][k]*W2[k][o] ----
        // lane covers o in {lane, lane+32}
        u64 a2[EPW][2];
#pragma unroll
        for (int e = 0; e < EPW; e++) { a2[e][0] = 0ull; a2[e][1] = 0ull; }

#pragma unroll 2
        for (int kk2 = 0; kk2 < HID / 4; kk2++) {      // 32 iters
            ulonglong2 w0 = *(const ulonglong2*)(W2T + lane * W2T_STRIDE + 4 * kk2);
            ulonglong2 w1 = *(const ulonglong2*)(W2T + (lane + 32) * W2T_STRIDE + 4 * kk2);
#pragma unroll
            for (int e = 0; e < EPW; e++) {
                ulonglong2 h2 = *(const ulonglong2*)(hw + e * HID + 4 * kk2);  // LDS.128 broadcast
                a2[e][0] = fma2(h2.x, w0.x, a2[e][0]);
                a2[e][0] = fma2(h2.y, w0.y, a2[e][0]);
                a2[e][1] = fma2(h2.x, w1.x, a2[e][1]);
                a2[e][1] = fma2(h2.y, w1.y, a2[e][1]);
            }
        }

        // ---- epilogue: fold halves, add bias, coalesced store ----
#pragma unroll
        for (int e = 0; e < EPW; e++) {
            float2 p0 = unpack2(a2[e][0]);
            float2 p1 = unpack2(a2[e][1]);
            size_t ob = (size_t)(ebase + e) * OUT_DIM;
            out[ob + lane]      = p0.x + p0.y + b2v[0];
            out[ob + lane + 32] = p1.x + p1.y + b2v[1];
        }
        __syncwarp();   // before next tile overwrites mw/hw
    }
}

extern "C" void kernel_launch(void* const* d_in, const int* in_sizes, int n_in,
                              void* d_out, int out_size)
{
    const float* x  = (const float*)d_in[0];
    const float* ea = (const float*)d_in[1];
    const float* W1 = (const float*)d_in[2];
    const float* b1 = (const float*)d_in[3];
    const float* W2 = (const float*)d_in[4];
    const float* b2 = (const float*)d_in[5];
    const void*  ei = d_in[6];
    float* out = (float*)d_out;

    cudaFuncSetAttribute(edge_mlp_kernel,
                         cudaFuncAttributeMaxDynamicSharedMemorySize, SMEM_BYTES);

    detect_idx_dtype_kernel<<<1, 256>>>((const unsigned int*)ei);
    edge_mlp_kernel<<<1472, NTHREADS, SMEM_BYTES>>>(x, ea, W1, b1, W2, b2, ei, out);
}